// round 4
// baseline (speedup 1.0000x reference)
#include <cuda_runtime.h>
#include <cstdint>

// Problem dims
#define PD1   128
#define PD2   128
#define PB    16
#define PSIN  64
#define PSOUT 128
// a / h layout: [i][j][b][s] row-major, s fastest.
// offset = i*262144 + j*2048 + b*128 + s   (floats)

typedef unsigned long long ull_t;

// ---------------- packed f32x2 helpers ----------------
__device__ __forceinline__ ull_t pack2(float x) {
    unsigned int xi = __float_as_uint(x);
    ull_t r;
    asm("mov.b64 %0, {%1, %1};" : "=l"(r) : "r"(xi));
    return r;
}
__device__ __forceinline__ void ffma2(ull_t &d, ull_t a, ull_t b) {
    asm("fma.rn.f32x2 %0, %1, %2, %0;" : "+l"(d) : "l"(a), "l"(b));
}
__device__ __forceinline__ float tanh_fast(float z) {
    // tanh(z) = 1 - 2/(exp(2z)+1) via MUFU ex2 + rcp (err ~1e-6)
    float e;
    asm("ex2.approx.f32 %0, %1;" : "=f"(e) : "f"(z * 2.8853900817779268f));
    float rc;
    asm("rcp.approx.f32 %0, %1;" : "=f"(rc) : "f"(e + 1.0f));
    return fmaf(-2.0f, rc, 1.0f);
}

// ---------------- Kernel 1: a = x @ w + bias  (into d_out) ----------------
// Block tile 128m x 128n, 256 threads, micro-tile 8m x 8n (as 4 f32x2 segs).
// K=64 in two 32-wide phases. 32 ULL accumulators = 64 regs (no spills).
#define XS_LD 36
__global__ __launch_bounds__(256)
void mdrnn_gemm_kernel(const float* __restrict__ X, const float* __restrict__ W,
                       const float* __restrict__ Bias, float* __restrict__ A) {
    __shared__ float xs[128 * XS_LD];   // 18432 B
    __shared__ float ws[32 * 128];      // 16384 B

    const int tid   = threadIdx.x;
    const int mtile = blockIdx.x;                 // 2048 tiles of 128 rows
    const float* Xb = X + (size_t)mtile * 128 * PSIN;

    const int tidm = tid >> 4;        // 0..15  -> m0 = tidm*8
    const int tidn = tid & 15;        // 0..15  -> n  = tidn*2 + seg*32
    const int m0   = tidm * 8;
    const int n0   = tidn * 2;

    ull_t acc[8][4];
#pragma unroll
    for (int mi = 0; mi < 8; mi++)
#pragma unroll
        for (int seg = 0; seg < 4; seg++) acc[mi][seg] = 0ULL;

    for (int kk = 0; kk < PSIN; kk += 32) {
        __syncthreads();
        // x half-tile: 128 rows x 32 k = 1024 float4, 4 per thread
#pragma unroll
        for (int q = 0; q < 4; q++) {
            int id  = tid + 256 * q;
            int row = id >> 3;
            int kq  = id & 7;
            *(float4*)&xs[row * XS_LD + kq * 4] =
                *(const float4*)(Xb + row * PSIN + kk + kq * 4);
        }
        // w half-tile: 32 k x 128 n = 1024 float4, 4 per thread
#pragma unroll
        for (int q = 0; q < 4; q++) {
            int id = tid + 256 * q;
            int k  = id >> 5;
            int nq = id & 31;
            *(float4*)&ws[k * 128 + nq * 4] =
                *(const float4*)(W + (size_t)(kk + k) * PSOUT + nq * 4);
        }
        __syncthreads();

#pragma unroll 4
        for (int k = 0; k < 32; k++) {
            ull_t wv[4];
#pragma unroll
            for (int seg = 0; seg < 4; seg++)
                wv[seg] = *(const ull_t*)&ws[k * 128 + n0 + seg * 32];
#pragma unroll
            for (int mi = 0; mi < 8; mi++) {
                ull_t xp = pack2(xs[(m0 + mi) * XS_LD + k]);
#pragma unroll
                for (int seg = 0; seg < 4; seg++) ffma2(acc[mi][seg], xp, wv[seg]);
            }
        }
    }

    float2 bv[4];
#pragma unroll
    for (int seg = 0; seg < 4; seg++)
        bv[seg] = *(const float2*)(Bias + n0 + seg * 32);

#pragma unroll
    for (int mi = 0; mi < 8; mi++) {
        float* out = A + ((size_t)mtile * 128 + m0 + mi) * PSOUT;
#pragma unroll
        for (int seg = 0; seg < 4; seg++) {
            uint2 u = *(uint2*)&acc[mi][seg];
            float2 o;
            o.x = __uint_as_float(u.x) + bv[seg].x;
            o.y = __uint_as_float(u.y) + bv[seg].y;
            *(float2*)(out + n0 + seg * 32) = o;
        }
    }
}

// ---------------- Kernel 2: 2D recurrence, wavefront, in place, float2 ----------------
// Block = (b, 8-s chunk): 256 blocks, 512 threads = 128 i x 4 s-pairs.
// All memory ops are 64-bit; warp load = 8 rows x 32B fully-used sectors.
// 256 diagonal steps; h[i-1][j] exchanged via double-buffered float2 smem.
//
// Prefetch ring alignment: slot (t & 3) is consumed at step t; thread i's
// first active step is t = i (j = 0), so a[j=q] must be seeded into slot
// (i + q) & 3. Refill of slot t&3 with j+4 is consumed at t+4 -> same slot.
__global__ __launch_bounds__(512, 3)
void mdrnn_scan_kernel(const float* __restrict__ U, float* __restrict__ H) {
    __shared__ float2 sh[2][512];

    const int tid = threadIdx.x;
    const int i   = tid >> 2;          // row 0..127
    const int sp  = tid & 3;           // s-pair 0..3
    const int b   = blockIdx.x >> 4;   // 0..15
    const int chk = blockIdx.x & 15;   // 0..15
    const int sg  = chk * 8 + sp * 2;  // global s (even)

    const float2 u0 = *(const float2*)(U + sg);
    const float2 u1 = *(const float2*)(U + PSOUT + sg);

    // float2 view; j-stride = 2048 floats = 1024 float2
    float2* Hb = (float2*)(H + (size_t)i * (PD2 * PB * PSOUT) + (size_t)b * PSOUT + sg);

    // depth-4 prefetch ring, seeded with rotation so slot (i+q)&3 <- a[j=q]
    float2 r[4];
#pragma unroll
    for (int q = 0; q < 4; q++) r[(i + q) & 3] = Hb[(size_t)q * 1024];

    float2 hl = make_float2(0.f, 0.f);

#pragma unroll 4
    for (int t = 0; t < 256; t++) {
        const int j = t - i;
        if ((unsigned)j < 128u) {
            float2 hup = make_float2(0.f, 0.f);
            if (i > 0) hup = sh[(t & 1) ^ 1][tid - 4];
            float2 a = r[t & 3];
            float zx = fmaf(hup.x, u0.x, a.x);
            float zy = fmaf(hup.y, u0.y, a.y);
            zx = fmaf(hl.x, u1.x, zx);
            zy = fmaf(hl.y, u1.y, zy);
            hl.x = tanh_fast(zx);
            hl.y = tanh_fast(zy);
            sh[t & 1][tid] = hl;
            Hb[(size_t)j * 1024] = hl;
            int j4 = j + 4;
            if (j4 < 128) r[t & 3] = Hb[(size_t)j4 * 1024];
        }
        __syncthreads();
    }
}

// ---------------- launch ----------------
extern "C" void kernel_launch(void* const* d_in, const int* in_sizes, int n_in,
                              void* d_out, int out_size) {
    const float* X    = (const float*)d_in[0];   // (128,128,16,64)
    const float* W    = (const float*)d_in[1];   // (64,128)
    const float* U    = (const float*)d_in[2];   // (2,128)
    const float* Bias = (const float*)d_in[3];   // (128,)
    float* H = (float*)d_out;                    // (128,128,16,128) — holds a, then h

    (void)in_sizes; (void)n_in; (void)out_size;

    mdrnn_gemm_kernel<<<2048, 256>>>(X, W, Bias, H);
    mdrnn_scan_kernel<<<256, 512>>>(U, H);
}